// round 3
// baseline (speedup 1.0000x reference)
#include <cuda_runtime.h>

typedef unsigned long long u64;
#define BATCH 131072

// inter-phase state: concat layout [b][96], enc at 0..63, cent at 64..95
__device__ float g_h0[(size_t)BATCH * 96];
__device__ float g_c0[(size_t)BATCH * 96];

__device__ __forceinline__ float ex2f(float x){ float y; asm("ex2.approx.f32 %0, %1;" : "=f"(y) : "f"(x)); return y; }
__device__ __forceinline__ float rcpf(float x){ float y; asm("rcp.approx.f32 %0, %1;" : "=f"(y) : "f"(x)); return y; }
__device__ __forceinline__ float sigmf(float x){ return rcpf(1.0f + ex2f(-1.4426950408889634f * x)); }
__device__ __forceinline__ float tanhf_(float x){ return 1.0f - 2.0f * rcpf(1.0f + ex2f(2.8853900817779268f * x)); }

// packed dual-fp32 FMA: d.lo += a.lo*b.lo ; d.hi += a.hi*b.hi
__device__ __forceinline__ void ffma2(u64 &d, u64 a, u64 b){
    asm("fma.rn.f32x2 %0, %1, %2, %0;" : "+l"(d) : "l"(a), "l"(b));
}
__device__ __forceinline__ float red2(u64 a){
    float lo, hi; asm("mov.b64 {%0, %1}, %2;" : "=f"(lo), "=f"(hi) : "l"(a)); return lo + hi;
}

// ---------------------------------------------------------------------------
// cent / enc phase. Thread = (element e, unit-chunk s). Full h in registers
// (u64 pairs). W broadcast from SMEM via LDS.128. c + h-exchange in SMEM rows.
// Unit interleave j = u*S + s keeps the S broadcast addresses in distinct
// bank quads (row stride H+4 => s offset = (H+4) floats = +4 banks).
// ---------------------------------------------------------------------------
template<int H, int T, int S, int NT, int OFF>
__global__ __launch_bounds__(NT)
void lstm_rec(const float* __restrict__ x_g,
              const float* __restrict__ Wih, const float* __restrict__ Whh,
              const float* __restrict__ bih, const float* __restrict__ bhh)
{
    constexpr int G  = 4 * H;
    constexpr int NE = NT / S;
    constexpr int UH = H / S;
    constexpr int WP = H + 4;
    constexpr int HP = H + 4;
    extern __shared__ float sm[];
    float* W  = sm;               // [G][WP]
    float* wx = W + G * WP;       // [G][2]
    float* bs = wx + G * 2;       // [G]
    float* cx = bs + G;           // [NE][HP]
    float* hx = cx + NE * HP;     // [NE][HP]

    const int tid = threadIdx.x;
    for (int i = tid; i < G * H; i += NT) W[(i / H) * WP + (i % H)] = Whh[i];
    for (int i = tid; i < G * 2; i += NT) wx[i] = Wih[i];
    for (int i = tid; i < G;     i += NT) bs[i] = bih[i] + bhh[i];
    __syncthreads();

    const int s = tid % S, e = tid / S;
    const size_t b = (size_t)blockIdx.x * NE + e;
    const float* xp = x_g + b * (size_t)(T * 2);
    float* crow = cx + e * HP;
    float* hrow = hx + e * HP;

    u64 hreg[H / 2];
    #pragma unroll
    for (int i = 0; i < H / 2; i++) hreg[i] = 0ULL;
    #pragma unroll 1
    for (int u = 0; u < UH; u++){ int j = u * S + s; crow[j] = 0.0f; }

    for (int t = 0; t < T; t++){
        const float2 xv = *(const float2*)(xp + 2 * t);
        #pragma unroll 1
        for (int u = 0; u < UH; u++){
            const int j = u * S + s;
            const float* Wj = W + j * WP;
            u64 a0[4], a1[4];
            #pragma unroll
            for (int r = 0; r < 4; r++){ a0[r] = 0ULL; a1[r] = 0ULL; }
            #pragma unroll
            for (int k4 = 0; k4 < H / 4; k4++){
                const u64 h0 = hreg[2 * k4], h1 = hreg[2 * k4 + 1];
                #pragma unroll
                for (int r = 0; r < 4; r++){
                    ulonglong2 wv = *(const ulonglong2*)(Wj + r * H * WP + 4 * k4);
                    ffma2(a0[r], wv.x, h0);
                    ffma2(a1[r], wv.y, h1);
                }
            }
            float gi = red2(a0[0]) + red2(a1[0]) + bs[j]       + xv.x * wx[2*j]           + xv.y * wx[2*j+1];
            float gf = red2(a0[1]) + red2(a1[1]) + bs[H+j]     + xv.x * wx[2*(H+j)]       + xv.y * wx[2*(H+j)+1];
            float gg = red2(a0[2]) + red2(a1[2]) + bs[2*H+j]   + xv.x * wx[2*(2*H+j)]     + xv.y * wx[2*(2*H+j)+1];
            float go = red2(a0[3]) + red2(a1[3]) + bs[3*H+j]   + xv.x * wx[2*(3*H+j)]     + xv.y * wx[2*(3*H+j)+1];
            float cv = sigmf(gf) * crow[j] + sigmf(gi) * tanhf_(gg);
            crow[j] = cv;
            hrow[j] = sigmf(go) * tanhf_(cv);
        }
        __syncwarp();
        #pragma unroll
        for (int k4 = 0; k4 < H / 4; k4++){
            ulonglong2 hv = *(const ulonglong2*)(hrow + 4 * k4);
            hreg[2 * k4] = hv.x; hreg[2 * k4 + 1] = hv.y;
        }
        __syncwarp();
    }

    const size_t gb = b * 96 + OFF;
    #pragma unroll 1
    for (int u = 0; u < UH; u++){
        const int j = u * S + s;
        g_h0[gb + j] = hrow[j];
        g_c0[gb + j] = crow[j];
    }
}

// ---------------------------------------------------------------------------
// decoder: H=96, 30 steps, x == h  =>  W = Wih+Whh, bias = bih+bhh.
// S=4 (24 units/thread), full h in registers, pos via SMEM dot + shfl fold.
// ---------------------------------------------------------------------------
#define DNT 256
__global__ __launch_bounds__(DNT)
void lstm_dec(const float* __restrict__ Wih, const float* __restrict__ Whh,
              const float* __restrict__ bih, const float* __restrict__ bhh,
              const float* __restrict__ Wemb, const float* __restrict__ bemb,
              float* __restrict__ out)
{
    constexpr int H = 96, G = 384, S = 4, NE = DNT / S, UH = H / S;
    constexpr int WP = H + 4, HP = H + 4;
    extern __shared__ float sm[];
    float* W  = sm;               // [384][WP]
    float* bs = W + G * WP;       // [384]
    float* we = bs + G;           // [192]
    float* cx = we + 192;         // [NE][HP]
    float* hx = cx + NE * HP;     // [NE][HP]

    const int tid = threadIdx.x;
    for (int i = tid; i < G * H; i += DNT) W[(i / H) * WP + (i % H)] = Wih[i] + Whh[i];
    for (int i = tid; i < G;     i += DNT) bs[i] = bih[i] + bhh[i];
    for (int i = tid; i < 192;   i += DNT) we[i] = Wemb[i];
    __syncthreads();

    const int s = tid % S, e = tid / S;
    const size_t b = (size_t)blockIdx.x * NE + e;
    float* crow = cx + e * HP;
    float* hrow = hx + e * HP;

    const size_t gb = b * 96;
    #pragma unroll 1
    for (int u = 0; u < UH; u++){
        const int j = u * S + s;
        crow[j] = g_c0[gb + j];
        hrow[j] = g_h0[gb + j];
    }
    __syncwarp();
    u64 hreg[H / 2];
    #pragma unroll
    for (int k4 = 0; k4 < H / 4; k4++){
        ulonglong2 hv = *(const ulonglong2*)(hrow + 4 * k4);
        hreg[2 * k4] = hv.x; hreg[2 * k4 + 1] = hv.y;
    }
    __syncwarp();

    const float bex = bemb[0], bey = bemb[1];
    float* op = out + b * 60;

    for (int t = 0; t < 30; t++){
        #pragma unroll 1
        for (int u = 0; u < UH; u++){
            const int j = u * S + s;
            const float* Wj = W + j * WP;
            u64 a0[4], a1[4];
            #pragma unroll
            for (int r = 0; r < 4; r++){ a0[r] = 0ULL; a1[r] = 0ULL; }
            #pragma unroll
            for (int k4 = 0; k4 < H / 4; k4++){
                const u64 h0 = hreg[2 * k4], h1 = hreg[2 * k4 + 1];
                #pragma unroll
                for (int r = 0; r < 4; r++){
                    ulonglong2 wv = *(const ulonglong2*)(Wj + r * H * WP + 4 * k4);
                    ffma2(a0[r], wv.x, h0);
                    ffma2(a1[r], wv.y, h1);
                }
            }
            float gi = red2(a0[0]) + red2(a1[0]) + bs[j];
            float gf = red2(a0[1]) + red2(a1[1]) + bs[H + j];
            float gg = red2(a0[2]) + red2(a1[2]) + bs[2*H + j];
            float go = red2(a0[3]) + red2(a1[3]) + bs[3*H + j];
            float cv = sigmf(gf) * crow[j] + sigmf(gi) * tanhf_(gg);
            crow[j] = cv;
            hrow[j] = sigmf(go) * tanhf_(cv);
        }
        __syncwarp();
        #pragma unroll
        for (int k4 = 0; k4 < H / 4; k4++){
            ulonglong2 hv = *(const ulonglong2*)(hrow + 4 * k4);
            hreg[2 * k4] = hv.x; hreg[2 * k4 + 1] = hv.y;
        }
        // pos: partial dot over k in [24s, 24s+24) from SMEM, fold across 4 lanes
        u64 ax = 0ULL, ay = 0ULL;
        const u64* hp  = (const u64*)(hrow + s * 24);
        const u64* wxp = (const u64*)(we + s * 24);
        const u64* wyp = (const u64*)(we + 96 + s * 24);
        #pragma unroll
        for (int i = 0; i < 12; i++){
            ffma2(ax, hp[i], wxp[i]);
            ffma2(ay, hp[i], wyp[i]);
        }
        __syncwarp();
        float px = red2(ax), py = red2(ay);
        px += __shfl_xor_sync(0xffffffffu, px, 1);
        px += __shfl_xor_sync(0xffffffffu, px, 2);
        py += __shfl_xor_sync(0xffffffffu, py, 1);
        py += __shfl_xor_sync(0xffffffffu, py, 2);
        if (s == 0){
            float2 o; o.x = px + bex; o.y = py + bey;
            *(float2*)(op + 2 * t) = o;
        }
    }
}

extern "C" void kernel_launch(void* const* d_in, const int* in_sizes, int n_in,
                              void* d_out, int out_size)
{
    (void)n_in; (void)out_size;
    const float* traj  = (const float*)d_in[0];
    const float* cent  = (const float*)d_in[1];
    const float* Wih_c = (const float*)d_in[2];
    const float* Whh_c = (const float*)d_in[3];
    const float* bih_c = (const float*)d_in[4];
    const float* bhh_c = (const float*)d_in[5];
    const float* Wih_e = (const float*)d_in[6];
    const float* Whh_e = (const float*)d_in[7];
    const float* bih_e = (const float*)d_in[8];
    const float* bhh_e = (const float*)d_in[9];
    const float* Wih_d = (const float*)d_in[10];
    const float* Whh_d = (const float*)d_in[11];
    const float* bih_d = (const float*)d_in[12];
    const float* bhh_d = (const float*)d_in[13];
    const float* W_emb = (const float*)d_in[14];
    const float* b_emb = (const float*)d_in[15];
    float* out = (float*)d_out;

    const int B = in_sizes[0] / 40;   // input_traj [B][20][2]

    // SMEM bytes: W[4H][H+4] + wx[4H][2] + bs[4H] + c[NE][H+4] + h[NE][H+4]
    const int smc = (128*36 + 128*2 + 128 + 256*36 + 256*36) * 4;   //  93,696
    const int sme = (256*68 + 256*2 + 256 + 128*68 + 128*68) * 4;   // 142,336
    const int smd = (384*100 + 384 + 192 + 64*100 + 64*100) * 4;    // 207,104

    cudaFuncSetAttribute(lstm_rec<32,100,1,256,64>, cudaFuncAttributeMaxDynamicSharedMemorySize, smc);
    cudaFuncSetAttribute(lstm_rec<64, 20,2,256, 0>, cudaFuncAttributeMaxDynamicSharedMemorySize, sme);
    cudaFuncSetAttribute(lstm_dec, cudaFuncAttributeMaxDynamicSharedMemorySize, smd);

    // centerline LSTM (H=32, T=100) -> g_h0/g_c0[.., 64..95]
    lstm_rec<32,100,1,256,64><<<B/256, 256, smc>>>(cent, Wih_c, Whh_c, bih_c, bhh_c);
    // encoder LSTM (H=64, T=20)    -> g_h0/g_c0[.., 0..63]
    lstm_rec<64, 20,2,256, 0><<<B/128, 256, sme>>>(traj, Wih_e, Whh_e, bih_e, bhh_e);
    // decoder (H=96, 30 steps) -> out [B][30][2]
    lstm_dec<<<B/64, 256, smd>>>(Wih_d, Whh_d, bih_d, bhh_d, W_emb, b_emb, out);
}

// round 4
// speedup vs baseline: 2.1904x; 2.1904x over previous
#include <cuda_runtime.h>

typedef unsigned long long u64;
#define BATCH 131072

// inter-phase state: concat layout [b][96], enc at 0..63, cent at 64..95
__device__ float g_h0[(size_t)BATCH * 96];
__device__ float g_c0[(size_t)BATCH * 96];

__device__ __forceinline__ float ex2f(float x){ float y; asm("ex2.approx.f32 %0, %1;" : "=f"(y) : "f"(x)); return y; }
__device__ __forceinline__ float rcpf(float x){ float y; asm("rcp.approx.f32 %0, %1;" : "=f"(y) : "f"(x)); return y; }
__device__ __forceinline__ float sigmf(float x){ return rcpf(1.0f + ex2f(-1.4426950408889634f * x)); }
__device__ __forceinline__ float tanhf_(float x){ return 1.0f - 2.0f * rcpf(1.0f + ex2f(2.8853900817779268f * x)); }

// packed dual-fp32 FMA: d.lo += a.lo*b.lo ; d.hi += a.hi*b.hi
__device__ __forceinline__ void ffma2(u64 &d, u64 a, u64 b){
    asm("fma.rn.f32x2 %0, %1, %2, %0;" : "+l"(d) : "l"(a), "l"(b));
}
__device__ __forceinline__ u64 dup2(float w){
    u64 r; asm("mov.b64 %0, {%1, %1};" : "=l"(r) : "f"(w)); return r;
}
__device__ __forceinline__ float2 u2f(u64 a){
    float2 r; asm("mov.b64 {%0, %1}, %2;" : "=f"(r.x), "=f"(r.y) : "l"(a)); return r;
}
__device__ __forceinline__ u64 f2u(float2 v){
    u64 r; asm("mov.b64 %0, {%1, %2};" : "=l"(r) : "f"(v.x), "f"(v.y)); return r;
}

// ---------------------------------------------------------------------------
// cent / enc recurrent phase, register-tiled outer product.
// Thread = (rt = unit-pair, et = 8-element tile). Computes gates for
// rows {j0,j0+1}+{0,H,2H,3H} x 8 elems, element-packed f32x2 accumulators.
// h stored [k][e] (e contiguous, row pad -> stride%128B=16): conflict-free.
// W[G][H+1] scalar, broadcast LDS.32 per (row,k), dup'd to (w,w).
// ---------------------------------------------------------------------------
template<int H, int T, int NT, int ETC, int OFF>
__global__ __launch_bounds__(NT)
void lstm_rec(const float* __restrict__ x_g,
              const float* __restrict__ Wih, const float* __restrict__ Whh,
              const float* __restrict__ bih, const float* __restrict__ bhh)
{
    constexpr int G  = 4 * H;
    constexpr int NE = ETC * 8;
    constexpr int WP = H + 1;
    constexpr int HP = NE + 4;
    extern __shared__ float sm[];
    float* hsm = sm;                 // [H][HP]
    float* Wd  = hsm + H * HP;       // [G][WP]
    float* bsd = Wd + G * WP;        // [G][2] dup'd bias
    float* xs0 = bsd + 2 * G;        // [2][NE]
    float* xs1 = xs0 + 2 * NE;       // [2][NE]

    const int tid = threadIdx.x;
    for (int i = tid; i < G * H; i += NT) Wd[(i / H) * WP + (i % H)] = Whh[i];
    for (int i = tid; i < G; i += NT){ float bv = bih[i] + bhh[i]; bsd[2*i] = bv; bsd[2*i+1] = bv; }
    for (int i = tid; i < H * HP; i += NT) hsm[i] = 0.0f;

    const int et = tid % ETC, rt = tid / ETC;
    const int j0 = rt * 2, e0 = et * 8;
    const size_t b0 = (size_t)blockIdx.x * NE;

    // per-thread x-projection weights [gate][uu][x-dim]
    float wxr[4][2][2];
    #pragma unroll
    for (int gt = 0; gt < 4; gt++)
        #pragma unroll
        for (int uu = 0; uu < 2; uu++){
            wxr[gt][uu][0] = Wih[(gt * H + j0 + uu) * 2];
            wxr[gt][uu][1] = Wih[(gt * H + j0 + uu) * 2 + 1];
        }

    u64 cc[2][4];
    #pragma unroll
    for (int uu = 0; uu < 2; uu++)
        #pragma unroll
        for (int ep = 0; ep < 4; ep++) cc[uu][ep] = 0ULL;

    // stage x[0] into buffer 0
    if (tid < NE){
        float2 v = *(const float2*)(x_g + (b0 + tid) * (size_t)(2 * T));
        xs0[tid] = v.x; xs1[tid] = v.y;
    }
    __syncthreads();

    for (int t = 0; t < T; t++){
        const int cur = t & 1, nxt = cur ^ 1;
        float2 xn = make_float2(0.f, 0.f);
        if (t + 1 < T && tid < NE)
            xn = *(const float2*)(x_g + (b0 + tid) * (size_t)(2 * T) + 2 * (t + 1));

        u64 acc[4][2][4];
        #pragma unroll
        for (int gt = 0; gt < 4; gt++)
            #pragma unroll
            for (int uu = 0; uu < 2; uu++){
                u64 bv = *(const u64*)&bsd[2 * (gt * H + j0 + uu)];
                #pragma unroll
                for (int ep = 0; ep < 4; ep++) acc[gt][uu][ep] = bv;
            }

        const float* hk = hsm + e0;
        #pragma unroll 4
        for (int k = 0; k < H; k++){
            ulonglong2 ha = *(const ulonglong2*)(hk);
            ulonglong2 hb = *(const ulonglong2*)(hk + 4);
            #pragma unroll
            for (int gt = 0; gt < 4; gt++)
                #pragma unroll
                for (int uu = 0; uu < 2; uu++){
                    u64 wd = dup2(Wd[(gt * H + j0 + uu) * WP + k]);
                    ffma2(acc[gt][uu][0], wd, ha.x);
                    ffma2(acc[gt][uu][1], wd, ha.y);
                    ffma2(acc[gt][uu][2], wd, hb.x);
                    ffma2(acc[gt][uu][3], wd, hb.y);
                }
            hk += HP;
        }

        float x0v[8], x1v[8];
        #pragma unroll
        for (int i = 0; i < 8; i++){ x0v[i] = xs0[cur * NE + e0 + i]; x1v[i] = xs1[cur * NE + e0 + i]; }

        float hnv[2][8];
        #pragma unroll
        for (int uu = 0; uu < 2; uu++)
            #pragma unroll
            for (int ep = 0; ep < 4; ep++){
                float2 gi = u2f(acc[0][uu][ep]);
                float2 gf = u2f(acc[1][uu][ep]);
                float2 gg = u2f(acc[2][uu][ep]);
                float2 go = u2f(acc[3][uu][ep]);
                float2 cv = u2f(cc[uu][ep]);
                #pragma unroll
                for (int m = 0; m < 2; m++){
                    const int e = 2 * ep + m;
                    float giX = (m ? gi.y : gi.x) + x0v[e] * wxr[0][uu][0] + x1v[e] * wxr[0][uu][1];
                    float gfX = (m ? gf.y : gf.x) + x0v[e] * wxr[1][uu][0] + x1v[e] * wxr[1][uu][1];
                    float ggX = (m ? gg.y : gg.x) + x0v[e] * wxr[2][uu][0] + x1v[e] * wxr[2][uu][1];
                    float goX = (m ? go.y : go.x) + x0v[e] * wxr[3][uu][0] + x1v[e] * wxr[3][uu][1];
                    float cn = sigmf(gfX) * (m ? cv.y : cv.x) + sigmf(giX) * tanhf_(ggX);
                    if (m) cv.y = cn; else cv.x = cn;
                    hnv[uu][e] = sigmf(goX) * tanhf_(cn);
                }
                cc[uu][ep] = f2u(cv);
            }

        __syncthreads();   // all h reads of this step done
        if (t + 1 < T && tid < NE){ xs0[nxt * NE + tid] = xn.x; xs1[nxt * NE + tid] = xn.y; }
        #pragma unroll
        for (int uu = 0; uu < 2; uu++){
            float* hw = hsm + (j0 + uu) * HP + e0;
            *(float4*)hw       = make_float4(hnv[uu][0], hnv[uu][1], hnv[uu][2], hnv[uu][3]);
            *(float4*)(hw + 4) = make_float4(hnv[uu][4], hnv[uu][5], hnv[uu][6], hnv[uu][7]);
        }
        __syncthreads();   // h update visible
    }

    // epilogue: write h/c into concat state
    #pragma unroll
    for (int uu = 0; uu < 2; uu++)
        #pragma unroll
        for (int ep = 0; ep < 4; ep++){
            float2 cv = u2f(cc[uu][ep]);
            const int j = j0 + uu;
            size_t gb0 = (b0 + e0 + 2 * ep) * 96 + OFF + j;
            size_t gb1 = (b0 + e0 + 2 * ep + 1) * 96 + OFF + j;
            g_h0[gb0] = hsm[j * HP + e0 + 2 * ep];
            g_h0[gb1] = hsm[j * HP + e0 + 2 * ep + 1];
            g_c0[gb0] = cv.x;
            g_c0[gb1] = cv.y;
        }
}

// ---------------------------------------------------------------------------
// decoder: H=96, 30 steps, x == h -> W = Wih+Whh, bias = bih+bhh.
// Same tiling; NT=384 (48 rt x 8 et), NE=64. pos via packed (x,y) dot.
// ---------------------------------------------------------------------------
#define DNT 384
__global__ __launch_bounds__(DNT)
void lstm_dec(const float* __restrict__ Wih, const float* __restrict__ Whh,
              const float* __restrict__ bih, const float* __restrict__ bhh,
              const float* __restrict__ Wemb, const float* __restrict__ bemb,
              float* __restrict__ out)
{
    constexpr int H = 96, G = 384, ETC = 8, NE = ETC * 8, WP = H + 1, HP = NE + 4;
    extern __shared__ float sm[];
    float* hsm = sm;                 // [H][HP]
    float* Wd  = hsm + H * HP;       // [G][WP]
    float* bsd = Wd + G * WP;        // [G][2]
    float* we2 = bsd + 2 * G;        // [H][2] (wex, wey) interleaved

    const int tid = threadIdx.x;
    for (int i = tid; i < G * H; i += DNT) Wd[(i / H) * WP + (i % H)] = Wih[i] + Whh[i];
    for (int i = tid; i < G; i += DNT){ float bv = bih[i] + bhh[i]; bsd[2*i] = bv; bsd[2*i+1] = bv; }
    for (int i = tid; i < H; i += DNT){ we2[2*i] = Wemb[i]; we2[2*i+1] = Wemb[96 + i]; }

    const int et = tid % ETC, rt = tid / ETC;
    const int j0 = rt * 2, e0 = et * 8;
    const size_t b0 = (size_t)blockIdx.x * NE;

    // load initial h into SMEM [j][e]
    for (int i = tid; i < H * NE; i += DNT){
        int j = i / NE, e = i % NE;
        hsm[j * HP + e] = g_h0[(b0 + e) * 96 + j];
    }
    // c packed in registers
    u64 cc[2][4];
    #pragma unroll
    for (int uu = 0; uu < 2; uu++)
        #pragma unroll
        for (int ep = 0; ep < 4; ep++){
            float2 cv;
            cv.x = g_c0[(b0 + e0 + 2 * ep)     * 96 + j0 + uu];
            cv.y = g_c0[(b0 + e0 + 2 * ep + 1) * 96 + j0 + uu];
            cc[uu][ep] = f2u(cv);
        }
    const float bex = bemb[0], bey = bemb[1];
    __syncthreads();

    for (int t = 0; t < 30; t++){
        u64 acc[4][2][4];
        #pragma unroll
        for (int gt = 0; gt < 4; gt++)
            #pragma unroll
            for (int uu = 0; uu < 2; uu++){
                u64 bv = *(const u64*)&bsd[2 * (gt * H + j0 + uu)];
                #pragma unroll
                for (int ep = 0; ep < 4; ep++) acc[gt][uu][ep] = bv;
            }

        const float* hk = hsm + e0;
        #pragma unroll 4
        for (int k = 0; k < H; k++){
            ulonglong2 ha = *(const ulonglong2*)(hk);
            ulonglong2 hb = *(const ulonglong2*)(hk + 4);
            #pragma unroll
            for (int gt = 0; gt < 4; gt++)
                #pragma unroll
                for (int uu = 0; uu < 2; uu++){
                    u64 wd = dup2(Wd[(gt * H + j0 + uu) * WP + k]);
                    ffma2(acc[gt][uu][0], wd, ha.x);
                    ffma2(acc[gt][uu][1], wd, ha.y);
                    ffma2(acc[gt][uu][2], wd, hb.x);
                    ffma2(acc[gt][uu][3], wd, hb.y);
                }
            hk += HP;
        }

        float hnv[2][8];
        #pragma unroll
        for (int uu = 0; uu < 2; uu++)
            #pragma unroll
            for (int ep = 0; ep < 4; ep++){
                float2 gi = u2f(acc[0][uu][ep]);
                float2 gf = u2f(acc[1][uu][ep]);
                float2 gg = u2f(acc[2][uu][ep]);
                float2 go = u2f(acc[3][uu][ep]);
                float2 cv = u2f(cc[uu][ep]);
                #pragma unroll
                for (int m = 0; m < 2; m++){
                    float cn = sigmf(m ? gf.y : gf.x) * (m ? cv.y : cv.x)
                             + sigmf(m ? gi.y : gi.x) * tanhf_(m ? gg.y : gg.x);
                    if (m) cv.y = cn; else cv.x = cn;
                    hnv[uu][2 * ep + m] = sigmf(m ? go.y : go.x) * tanhf_(cn);
                }
                cc[uu][ep] = f2u(cv);
            }

        __syncthreads();
        #pragma unroll
        for (int uu = 0; uu < 2; uu++){
            float* hw = hsm + (j0 + uu) * HP + e0;
            *(float4*)hw       = make_float4(hnv[uu][0], hnv[uu][1], hnv[uu][2], hnv[uu][3]);
            *(float4*)(hw + 4) = make_float4(hnv[uu][4], hnv[uu][5], hnv[uu][6], hnv[uu][7]);
        }
        __syncthreads();

        // pos output: 64 threads, one element each, packed (x,y) dot
        if (tid < NE){
            u64 ap = 0ULL;
            const float* hp = hsm + tid;
            #pragma unroll 8
            for (int j = 0; j < H; j++){
                u64 hd = dup2(hp[j * HP]);
                ffma2(ap, hd, *(const u64*)&we2[2 * j]);
            }
            float2 p = u2f(ap);
            float2 o; o.x = p.x + bex; o.y = p.y + bey;
            *(float2*)(out + (b0 + tid) * 60 + 2 * t) = o;
        }
    }
}

extern "C" void kernel_launch(void* const* d_in, const int* in_sizes, int n_in,
                              void* d_out, int out_size)
{
    (void)n_in; (void)out_size;
    const float* traj  = (const float*)d_in[0];
    const float* cent  = (const float*)d_in[1];
    const float* Wih_c = (const float*)d_in[2];
    const float* Whh_c = (const float*)d_in[3];
    const float* bih_c = (const float*)d_in[4];
    const float* bhh_c = (const float*)d_in[5];
    const float* Wih_e = (const float*)d_in[6];
    const float* Whh_e = (const float*)d_in[7];
    const float* bih_e = (const float*)d_in[8];
    const float* bhh_e = (const float*)d_in[9];
    const float* Wih_d = (const float*)d_in[10];
    const float* Whh_d = (const float*)d_in[11];
    const float* bih_d = (const float*)d_in[12];
    const float* bhh_d = (const float*)d_in[13];
    const float* W_emb = (const float*)d_in[14];
    const float* b_emb = (const float*)d_in[15];
    float* out = (float*)d_out;

    const int B = in_sizes[0] / 40;   // input_traj [B][20][2]

    // SMEM (floats): h[H][NE+4] + W[4H][H+1] + bias-dup[4H][2] + x stage
    const int smc = (32*132 + 128*33 + 256 + 512) * 4;        //  36,864 B  (NE=128)
    const int sme = (64*68 + 256*65 + 512 + 256) * 4;         //  87,040 B  (NE=64)
    const int smd = (96*68 + 384*97 + 768 + 192) * 4;         // 178,944 B  (NE=64)

    cudaFuncSetAttribute(lstm_rec<32,100,256,16,64>, cudaFuncAttributeMaxDynamicSharedMemorySize, smc);
    cudaFuncSetAttribute(lstm_rec<64, 20,256, 8, 0>, cudaFuncAttributeMaxDynamicSharedMemorySize, sme);
    cudaFuncSetAttribute(lstm_dec, cudaFuncAttributeMaxDynamicSharedMemorySize, smd);

    // centerline LSTM (H=32, T=100, NE=128) -> g_h0/g_c0[.., 64..95]
    lstm_rec<32,100,256,16,64><<<B/128, 256, smc>>>(cent, Wih_c, Whh_c, bih_c, bhh_c);
    // encoder LSTM (H=64, T=20, NE=64)      -> g_h0/g_c0[.., 0..63]
    lstm_rec<64, 20,256, 8, 0><<<B/64, 256, sme>>>(traj, Wih_e, Whh_e, bih_e, bhh_e);
    // decoder (H=96, 30 steps, NE=64) -> out [B][30][2]
    lstm_dec<<<B/64, DNT, smd>>>(Wih_d, Whh_d, bih_d, bhh_d, W_emb, b_emb, out);
}